// round 7
// baseline (speedup 1.0000x reference)
#include <cuda_runtime.h>
#include <cuda_bf16.h>
#include <math.h>
#include <stdint.h>

// Problem constants
#define BB 16
#define CC 1024
#define DD 768
#define TAU_INV 10.0f
#define KHARD 306
#define KRAND 717
#define SLOTS_PER_B 128
#define MAXP (BB * SLOTS_PER_B)   // 2048

// Split-bf16 GEMM: K' = 3*DD = 2304 bf16 (A=[hi|hi|lo], B=[hi|lo|hi])
#define KP 2304
#define ROWB (KP * 2)             // 4608 bytes per row
#define KC 64                     // K columns per chunk (128 B)
#define NCHUNK (KP / KC)          // 36
#define TILE_BYTES (128 * 128)    // 16 KB per operand tile
#define DYN_SMEM (2 * 2 * TILE_BYTES)   // 64 KB (2 stages x A+B)

// Static device scratch (zero-init at load; unused slot rows never written)
__device__ __align__(128) unsigned char g_Ab[(size_t)MAXP * ROWB];   // 9.4 MB bf16
__device__ __align__(128) unsigned char g_Bb[(size_t)CC * ROWB];     // 4.7 MB bf16
__device__ float g_S[(size_t)MAXP * CC];
__device__ int   g_posList[MAXP];
__device__ int   g_posCount[BB];
__device__ unsigned char g_randFlag[BB * CC];
__device__ float g_term[MAXP];

// ---------------------------------------------------------------------------
// helpers
// ---------------------------------------------------------------------------
__device__ __forceinline__ uint32_t smem_u32(const void* p) {
    uint32_t a;
    asm("{ .reg .u64 t; cvta.to.shared.u64 t, %1; cvt.u32.u64 %0, t; }" : "=r"(a) : "l"(p));
    return a;
}
__device__ __forceinline__ void cp16(uint32_t dst, const void* src) {
    asm volatile("cp.async.ca.shared.global [%0], [%1], 16;" :: "r"(dst), "l"(src) : "memory");
}
__device__ __forceinline__ void ldsm_x4(uint32_t& r0, uint32_t& r1, uint32_t& r2, uint32_t& r3,
                                        uint32_t a) {
    asm volatile("ldmatrix.sync.aligned.m8n8.x4.shared.b16 {%0,%1,%2,%3}, [%4];"
                 : "=r"(r0), "=r"(r1), "=r"(r2), "=r"(r3) : "r"(a));
}
__device__ __forceinline__ void ldsm_x2(uint32_t& r0, uint32_t& r1, uint32_t a) {
    asm volatile("ldmatrix.sync.aligned.m8n8.x2.shared.b16 {%0,%1}, [%2];"
                 : "=r"(r0), "=r"(r1) : "r"(a));
}
__device__ __forceinline__ void mma16816(float* c, const uint32_t* a, const uint32_t* b) {
    asm volatile("mma.sync.aligned.m16n8k16.row.col.f32.bf16.bf16.f32 "
                 "{%0,%1,%2,%3}, {%4,%5,%6,%7}, {%8,%9}, {%0,%1,%2,%3};"
                 : "+f"(c[0]), "+f"(c[1]), "+f"(c[2]), "+f"(c[3])
                 : "r"(a[0]), "r"(a[1]), "r"(a[2]), "r"(a[3]), "r"(b[0]), "r"(b[1]));
}
// order-preserving float<->uint key
__device__ __forceinline__ unsigned fkey(float f) {
    unsigned u = __float_as_uint(f);
    return (u & 0x80000000u) ? ~u : (u | 0x80000000u);
}
__device__ __forceinline__ float funkey(unsigned u) {
    return __uint_as_float((u & 0x80000000u) ? (u & 0x7fffffffu) : ~u);
}

union BF4 { __nv_bfloat16 h[4]; uint2 u; };

// ---------------------------------------------------------------------------
// Kernel 0 (fused): blocks [0,CC): normalize proto row, split bf16 hi/lo,
// write g_Bb row [hi|lo|hi]. Blocks [CC,CC+BB): compaction + random top-K.
// ---------------------------------------------------------------------------
__global__ void k_prep(const float* __restrict__ p,
                       const int* __restrict__ targets,
                       const float* __restrict__ rsc) {
    int tid = threadIdx.x;
    if (blockIdx.x < CC) {
        int e = blockIdx.x;
        const float4* row = (const float4*)(p + (size_t)e * DD);
        float4 v = make_float4(0,0,0,0);
        float ss = 0.f;
        if (tid < 192) {                      // DD/4 = 192 float4 segments
            v = row[tid];
            ss = v.x*v.x + v.y*v.y + v.z*v.z + v.w*v.w;
        }
        for (int o = 16; o > 0; o >>= 1) ss += __shfl_xor_sync(0xffffffffu, ss, o);
        __shared__ float sW[8]; __shared__ float sInv;
        if ((tid & 31) == 0) sW[tid >> 5] = ss;
        __syncthreads();
        if (tid == 0) {
            float t = 0.f;
            for (int w = 0; w < 8; w++) t += sW[w];
            sInv = 1.0f / fmaxf(sqrtf(t), 1e-12f);
        }
        __syncthreads();
        if (tid < 192) {
            float inv = sInv;
            float vv[4] = {v.x*inv, v.y*inv, v.z*inv, v.w*inv};
            BF4 hi, lo;
#pragma unroll
            for (int j = 0; j < 4; j++) {
                hi.h[j] = __float2bfloat16(vv[j]);
                lo.h[j] = __float2bfloat16(vv[j] - __bfloat162float(hi.h[j]));
            }
            unsigned char* dst = g_Bb + (size_t)e * ROWB + tid * 8;
            *(uint2*)(dst)                = hi.u;   // seg0: hi
            *(uint2*)(dst + DD * 2)       = lo.u;   // seg1: lo
            *(uint2*)(dst + 2 * DD * 2)   = hi.u;   // seg2: hi
        }
        return;
    }

    // ---- per-batch compaction + exact random top-KRAND ----
    int b = blockIdx.x - CC;
    __shared__ unsigned int skey[CC];
    __shared__ unsigned char sfl[CC];
    __shared__ int sW[8];
    __shared__ int sOut;

    int lane = tid & 31, wid = tid >> 5;
    int e0 = tid * 4;
    unsigned int key[4]; int posf[4]; int cnt = 0;
#pragma unroll
    for (int j = 0; j < 4; j++) {
        int e = e0 + j;
        int isPos = (targets[b * CC + e] != 0);
        posf[j] = isPos; cnt += isPos;
        unsigned int k = isPos ? 0u : (__float_as_uint(rsc[b * CC + e]) + 1u);
        key[j] = k; skey[e] = k;
    }
    int inc = cnt;
    for (int o = 1; o < 32; o <<= 1) {
        int v = __shfl_up_sync(0xffffffffu, inc, o);
        if (lane >= o) inc += v;
    }
    if (lane == 31) sW[wid] = inc;
    __syncthreads();
    if (tid == 0) {
        int acc = 0;
        for (int w = 0; w < 8; w++) { int v = sW[w]; sW[w] = acc; acc += v; }
        g_posCount[b] = acc;
    }
    __syncthreads();
    int rank = sW[wid] + inc - cnt;
#pragma unroll
    for (int j = 0; j < 4; j++) {
        if (posf[j]) {
            if (rank < SLOTS_PER_B) g_posList[b * SLOTS_PER_B + rank] = e0 + j;
            rank++;
        }
    }
    __syncthreads();

    unsigned lo = 0u, hi = 0xFFFFFFFFu;
    while (hi - lo > 1u) {
        unsigned mid = lo + ((hi - lo) >> 1);
        int c4 = 0;
#pragma unroll
        for (int j = 0; j < 4; j++) c4 += (key[j] >= mid);
        c4 = __reduce_add_sync(0xffffffffu, c4);
        if (lane == 0) sW[wid] = c4;
        __syncthreads();
        int total = sW[0]+sW[1]+sW[2]+sW[3]+sW[4]+sW[5]+sW[6]+sW[7];
        if (total >= KRAND) lo = mid; else hi = mid;
        __syncthreads();
    }
    unsigned V = lo;
    int both4 = 0;
#pragma unroll
    for (int j = 0; j < 4; j++) both4 += (key[j] > V) * 2048 + (key[j] == V);
    both4 = __reduce_add_sync(0xffffffffu, both4);
    if (lane == 0) sW[wid] = both4;
    __syncthreads();
    if (tid == 0) { int t = 0; for (int w = 0; w < 8; w++) t += sW[w]; sOut = t; }
    __syncthreads();
    int n_gt = sOut / 2048;
    int n_eq = sOut % 2048;
    int rrem = KRAND - n_gt;

    if (n_eq == rrem) {
#pragma unroll
        for (int j = 0; j < 4; j++) sfl[e0 + j] = (key[j] >= V) ? 1 : 0;
        __syncthreads();
    } else {
#pragma unroll
        for (int j = 0; j < 4; j++) sfl[e0 + j] = (key[j] > V) ? 1 : 0;
        __syncthreads();
        if (tid == 0) {
            int rem = rrem;
            for (int e = 0; e < CC && rem > 0; e++)
                if (skey[e] == V) { sfl[e] = 1; rem--; }
        }
        __syncthreads();
    }
#pragma unroll
    for (int j = 0; j < 4; j++) g_randFlag[b * CC + e0 + j] = sfl[e0 + j];
}

// ---------------------------------------------------------------------------
// Kernel 1: gather + normalize positive anchor rows, split bf16 hi/lo,
// write g_Ab row [hi|hi|lo].
// ---------------------------------------------------------------------------
__global__ void k_norm_f(const float* __restrict__ f) {
    int i = blockIdx.x;
    int b = i >> 7, r = i & 127;
    int cnt = g_posCount[b]; if (cnt > SLOTS_PER_B) cnt = SLOTS_PER_B;
    if (r >= cnt) return;
    int c = g_posList[i];
    int tid = threadIdx.x;

    const float4* src = (const float4*)(f + (size_t)(b * CC + c) * DD);
    float4 v0 = make_float4(0,0,0,0), v1 = make_float4(0,0,0,0);
    float ss = 0.f;
    if (tid < 96) {
        v0 = src[tid * 2]; v1 = src[tid * 2 + 1];
        ss = v0.x*v0.x + v0.y*v0.y + v0.z*v0.z + v0.w*v0.w
           + v1.x*v1.x + v1.y*v1.y + v1.z*v1.z + v1.w*v1.w;
    }
    for (int o = 16; o > 0; o >>= 1) ss += __shfl_xor_sync(0xffffffffu, ss, o);
    __shared__ float sW[4]; __shared__ float sInv;
    if ((tid & 31) == 0) sW[tid >> 5] = ss;
    __syncthreads();
    if (tid == 0) sInv = 1.0f / fmaxf(sqrtf(sW[0]+sW[1]+sW[2]+sW[3]), 1e-12f);
    __syncthreads();
    if (tid >= 96) return;
    float inv = sInv;
    float v[8] = {v0.x*inv, v0.y*inv, v0.z*inv, v0.w*inv,
                  v1.x*inv, v1.y*inv, v1.z*inv, v1.w*inv};
    BF4 hiA, loA, hiB, loB;
#pragma unroll
    for (int j = 0; j < 4; j++) {
        hiA.h[j] = __float2bfloat16(v[j]);
        loA.h[j] = __float2bfloat16(v[j] - __bfloat162float(hiA.h[j]));
        hiB.h[j] = __float2bfloat16(v[j + 4]);
        loB.h[j] = __float2bfloat16(v[j + 4] - __bfloat162float(hiB.h[j]));
    }
    unsigned char* dst = g_Ab + (size_t)i * ROWB + tid * 16;
    *(uint2*)(dst)                  = hiA.u;  *(uint2*)(dst + 8)              = hiB.u;  // seg0: hi
    *(uint2*)(dst + DD*2)           = hiA.u;  *(uint2*)(dst + DD*2 + 8)       = hiB.u;  // seg1: hi
    *(uint2*)(dst + 2*DD*2)         = loA.u;  *(uint2*)(dst + 2*DD*2 + 8)     = loB.u;  // seg2: lo
}

// ---------------------------------------------------------------------------
// Kernel 2: bf16 tensor-core GEMM via mma.sync m16n8k16 (unchanged, passing).
// ---------------------------------------------------------------------------
__global__ void __launch_bounds__(256, 1) k_gemm_mma() {
    extern __shared__ __align__(16) unsigned char dynsm[];
    int m = blockIdx.x;
    int cnt = g_posCount[m]; if (cnt <= 0) return;
    if (cnt > SLOTS_PER_B) cnt = SLOTS_PER_B;
    int eBase = blockIdx.y * 128;
    int tid = threadIdx.x, lane = tid & 31, wid = tid >> 5;
    int wm = (wid & 1) * 64, wn = (wid >> 1) * 32;

    uint32_t sbase = smem_u32(dynsm);
    const unsigned char* gA = g_Ab + (size_t)m * 128 * ROWB;
    const unsigned char* gB = g_Bb + (size_t)eBase * ROWB;

    float acc[4][4][4];
#pragma unroll
    for (int i = 0; i < 4; i++)
#pragma unroll
        for (int j = 0; j < 4; j++)
#pragma unroll
            for (int q = 0; q < 4; q++) acc[i][j][q] = 0.f;

    auto copy_chunk = [&](int c, int st) {
        uint32_t sA = sbase + st * (2 * TILE_BYTES);
        uint32_t sB = sA + TILE_BYTES;
#pragma unroll
        for (int i = 0; i < 4; i++) {
            int idx = tid + i * 256;
            int row = idx >> 3, seg = idx & 7;
            uint32_t so = (uint32_t)((row << 3) + (seg ^ (row & 7))) * 16;
            size_t go = (size_t)row * ROWB + c * 128 + seg * 16;
            cp16(sA + so, gA + go);
            cp16(sB + so, gB + go);
        }
        asm volatile("cp.async.commit_group;" ::: "memory");
    };

    copy_chunk(0, 0);
    for (int c = 0; c < NCHUNK; c++) {
        int cur = c & 1;
        if (c + 1 < NCHUNK) copy_chunk(c + 1, cur ^ 1);
        if (c + 1 < NCHUNK)
            asm volatile("cp.async.wait_group 1;" ::: "memory");
        else
            asm volatile("cp.async.wait_group 0;" ::: "memory");
        __syncthreads();

        uint32_t sA = sbase + cur * (2 * TILE_BYTES);
        uint32_t sB = sA + TILE_BYTES;
#pragma unroll
        for (int ks = 0; ks < 4; ks++) {
            uint32_t a[4][4], b[4][2];
#pragma unroll
            for (int mi = 0; mi < 4; mi++) {
                int row = wm + mi * 16 + (lane & 15);
                int kseg = 2 * ks + (lane >> 4);
                ldsm_x4(a[mi][0], a[mi][1], a[mi][2], a[mi][3],
                        sA + (uint32_t)((row << 3) + (kseg ^ (row & 7))) * 16);
            }
#pragma unroll
            for (int ni = 0; ni < 4; ni++) {
                int rn = wn + ni * 8 + (lane & 7);
                int kseg = 2 * ks + ((lane >> 3) & 1);
                ldsm_x2(b[ni][0], b[ni][1],
                        sB + (uint32_t)((rn << 3) + (kseg ^ (rn & 7))) * 16);
            }
#pragma unroll
            for (int mi = 0; mi < 4; mi++)
#pragma unroll
                for (int ni = 0; ni < 4; ni++)
                    mma16816(acc[mi][ni], a[mi], b[ni]);
        }
        __syncthreads();
    }

    int qr = lane >> 2, qc = (lane & 3) * 2;
#pragma unroll
    for (int mi = 0; mi < 4; mi++) {
#pragma unroll
        for (int ni = 0; ni < 4; ni++) {
            int r0 = wm + mi * 16 + qr;
            int col = eBase + wn + ni * 8 + qc;
            if (r0 < cnt)
                *(float2*)(g_S + (size_t)(m * 128 + r0) * CC + col)
                    = make_float2(acc[mi][ni][0], acc[mi][ni][1]);
            if (r0 + 8 < cnt)
                *(float2*)(g_S + (size_t)(m * 128 + r0 + 8) * CC + col)
                    = make_float2(acc[mi][ni][2], acc[mi][ni][3]);
        }
    }
}

// ---------------------------------------------------------------------------
// Kernel 3: per positive anchor: top-KHARD exp-sum via 3-pass 256-bin
// histogram descent (cell <= 2^8 key-ulps -> tie-value error ~5e-6),
// + random-set exp sum -> loss term.
// ---------------------------------------------------------------------------
__global__ void k_select(const int* __restrict__ targets) {
    int i = blockIdx.x;
    int b = i >> 7, r = i & 127;
    int cnt = g_posCount[b]; if (cnt > SLOTS_PER_B) cnt = SLOTS_PER_B;
    int tid = threadIdx.x;
    if (r >= cnt) { if (tid == 0) g_term[i] = 0.f; return; }
    int c = g_posList[i];

    __shared__ int hist[256];
    __shared__ unsigned sWmax[8];
    __shared__ unsigned sWmin[8];
    __shared__ int sQA[2];
    __shared__ float sWf[8];

    int lane = tid & 31, wid = tid >> 5;

    float4 s4 = *((const float4*)(g_S + (size_t)i * CC) + tid);
    int4   t4 = *((const int4*)(targets + b * CC) + tid);
    uchar4 r4 = *((const uchar4*)(g_randFlag + b * CC) + tid);
    float s[4] = {s4.x, s4.y, s4.z, s4.w};
    int neg[4] = {t4.x == 0, t4.y == 0, t4.z == 0, t4.w == 0};
    int fl[4]  = {r4.x, r4.y, r4.z, r4.w};
    unsigned key[4];
#pragma unroll
    for (int j = 0; j < 4; j++) key[j] = neg[j] ? fkey(s[j]) : 0u;

    // block max / min over negative keys (positives are key 0, never the max;
    // min masked to all-ones for positives)
    unsigned mk = max(max(key[0], key[1]), max(key[2], key[3]));
    unsigned nk0 = neg[0] ? key[0] : 0xffffffffu;
    unsigned nk1 = neg[1] ? key[1] : 0xffffffffu;
    unsigned nk2 = neg[2] ? key[2] : 0xffffffffu;
    unsigned nk3 = neg[3] ? key[3] : 0xffffffffu;
    unsigned nk = min(min(nk0, nk1), min(nk2, nk3));
    mk = __reduce_max_sync(0xffffffffu, mk);
    nk = __reduce_min_sync(0xffffffffu, nk);
    if (lane == 0) { sWmax[wid] = mk; sWmin[wid] = nk; }
    __syncthreads();
    unsigned mAll = sWmax[0], nAll = sWmin[0];
#pragma unroll
    for (int w = 1; w < 8; w++) { mAll = max(mAll, sWmax[w]); nAll = min(nAll, sWmin[w]); }
    float M = funkey(mAll);

    // 3-pass histogram descent: cell [lo, lo+range) always satisfies
    // above = count(key >= lo+range) < KHARD <= above + count(in cell)
    unsigned lo = nAll;
    unsigned range = mAll - nAll + 1u;
    unsigned step = 1u;
    int above = 0;
#pragma unroll
    for (int pass = 0; pass < 3; pass++) {
        step = range / 256u + 1u;
        hist[tid] = 0;
        __syncthreads();
#pragma unroll
        for (int j = 0; j < 4; j++) {
            unsigned d = key[j] - lo;            // wraps huge if key < lo
            if (d < range) atomicAdd(&hist[d / step], 1);
        }
        __syncthreads();
        if (wid == 0) {
            int h[8]; int ssum = 0;
            int base = lane * 8;
#pragma unroll
            for (int q = 0; q < 8; q++) { h[q] = hist[base + q]; ssum += h[q]; }
            // inclusive suffix over lanes
            int suf = ssum;
            for (int o = 1; o < 32; o <<= 1) {
                int v = __shfl_down_sync(0xffffffffu, suf, o);
                if (lane + o < 32) suf += v;
            }
            int hiAbove = above + suf - ssum;    // count >= this lane's top bin bound
            if (above + suf >= KHARD && hiAbove < KHARD) {   // exactly one lane
                int acc = hiAbove;
                int q = 7;
                for (; q > 0; q--) {
                    if (acc + h[q] >= KHARD) break;
                    acc += h[q];
                }
                sQA[0] = base + q;
                sQA[1] = acc;                    // = count(key >= cell_top of bin q)
            }
        }
        __syncthreads();
        int Q = sQA[0]; above = sQA[1];
        lo = lo + (unsigned)Q * step;
        range = step;
        __syncthreads();                          // protect sQA/hist reuse next pass
    }
    unsigned Hi = lo + step;                      // cell top
    int n_gt = above;                             // exact count(key >= Hi)
    int rem = KHARD - n_gt;                       // >= 1 ties in [lo, Hi)

    float es = 0.f;
#pragma unroll
    for (int j = 0; j < 4; j++) {
        float e = __expf((s[j] - M) * TAU_INV);
        if (key[j] >= Hi) es += e;                // hard negatives above cell
        if (fl[j])        es += e;                // random negatives
    }
    for (int o = 16; o > 0; o >>= 1) es += __shfl_xor_sync(0xffffffffu, es, o);
    if (lane == 0) sWf[wid] = es;
    __syncthreads();

    if (tid == 0) {
        float su = sWf[0]+sWf[1]+sWf[2]+sWf[3]+sWf[4]+sWf[5]+sWf[6]+sWf[7];
        su += (float)rem * __expf((funkey(lo) - M) * TAU_INV);   // ties at cell base
        float pos = g_S[(size_t)i * CC + c] * TAU_INV;
        float lse = M * TAU_INV + __logf(su);
        float d = lse - pos;
        float term = (d > 0.f) ? d + log1pf(__expf(-d)) : log1pf(__expf(d));
        g_term[i] = term;
    }
}

// ---------------------------------------------------------------------------
// Kernel 4: deterministic final reduction -> scalar loss
// ---------------------------------------------------------------------------
__global__ void k_final(float* __restrict__ out) {
    __shared__ float sbs[BB];
    int wid = threadIdx.x >> 5, lane = threadIdx.x & 31;
    float s = 0.f;
    for (int r = lane; r < SLOTS_PER_B; r += 32) s += g_term[wid * SLOTS_PER_B + r];
    for (int o = 16; o > 0; o >>= 1) s += __shfl_xor_sync(0xffffffffu, s, o);
    if (lane == 0) sbs[wid] = s;
    __syncthreads();
    if (threadIdx.x == 0) {
        float tot = 0.f;
        for (int b = 0; b < BB; b++) {
            int pc = g_posCount[b]; if (pc < 1) pc = 1;
            tot += sbs[b] / (float)pc;
        }
        out[0] = tot / (float)BB;
    }
}

extern "C" void kernel_launch(void* const* d_in, const int* in_sizes, int n_in,
                              void* d_out, int out_size) {
    const float* f       = (const float*)d_in[0];   // (B,C,D)
    const float* p       = (const float*)d_in[1];   // (C,D)
    const int*   targets = (const int*)  d_in[2];   // (B,C)
    const float* rsc     = (const float*)d_in[3];   // (B,C)
    float* out = (float*)d_out;

    cudaFuncSetAttribute(k_gemm_mma, cudaFuncAttributeMaxDynamicSharedMemorySize, DYN_SMEM);

    k_prep<<<CC + BB, 256>>>(p, targets, rsc);
    k_norm_f<<<MAXP, 128>>>(f);
    k_gemm_mma<<<dim3(BB, CC / 128), 256, DYN_SMEM>>>();
    k_select<<<MAXP, 256>>>(targets);
    k_final<<<1, 512>>>(out);
}

// round 8
// speedup vs baseline: 1.6533x; 1.6533x over previous
#include <cuda_runtime.h>
#include <cuda_bf16.h>
#include <math.h>
#include <stdint.h>

// Problem constants
#define BB 16
#define CC 1024
#define DD 768
#define TAU_INV 10.0f
#define KHARD 306
#define KRAND 717
#define SLOTS_PER_B 128
#define MAXP (BB * SLOTS_PER_B)   // 2048

// Split-bf16: rows stored as [hi|lo], K=1536 bf16 = 3072 B/row.
// GEMM runs 36 virtual chunks: (hiA,hiB) x12, (hiA,loB) x12, (loA,hiB) x12,
// paired via source-offset tables at cp.async time.
#define ROWB 3072
#define NCHUNK 36
#define KSPLIT 18                 // chunks per grid.z half
#define TILE_BYTES (128 * 128)    // 16 KB per operand tile
#define DYN_SMEM (2 * 2 * TILE_BYTES)   // 64 KB (2 stages x A+B)

// Static device scratch (zero-init at load; unused slot rows never written)
__device__ __align__(128) unsigned char g_Ab[(size_t)MAXP * ROWB];   // 6.3 MB
__device__ __align__(128) unsigned char g_Bb[(size_t)CC * ROWB];     // 3.1 MB
__device__ float g_S0[(size_t)MAXP * CC];    // split-K partial 0
__device__ float g_S1[(size_t)MAXP * CC];    // split-K partial 1
__device__ int   g_posList[MAXP];
__device__ int   g_posCount[BB];
__device__ unsigned char g_randFlag[BB * CC];
__device__ float g_term[MAXP];

// ---------------------------------------------------------------------------
// helpers
// ---------------------------------------------------------------------------
__device__ __forceinline__ uint32_t smem_u32(const void* p) {
    uint32_t a;
    asm("{ .reg .u64 t; cvta.to.shared.u64 t, %1; cvt.u32.u64 %0, t; }" : "=r"(a) : "l"(p));
    return a;
}
__device__ __forceinline__ void cp16(uint32_t dst, const void* src) {
    asm volatile("cp.async.ca.shared.global [%0], [%1], 16;" :: "r"(dst), "l"(src) : "memory");
}
__device__ __forceinline__ void ldsm_x4(uint32_t& r0, uint32_t& r1, uint32_t& r2, uint32_t& r3,
                                        uint32_t a) {
    asm volatile("ldmatrix.sync.aligned.m8n8.x4.shared.b16 {%0,%1,%2,%3}, [%4];"
                 : "=r"(r0), "=r"(r1), "=r"(r2), "=r"(r3) : "r"(a));
}
__device__ __forceinline__ void ldsm_x2(uint32_t& r0, uint32_t& r1, uint32_t a) {
    asm volatile("ldmatrix.sync.aligned.m8n8.x2.shared.b16 {%0,%1}, [%2];"
                 : "=r"(r0), "=r"(r1) : "r"(a));
}
__device__ __forceinline__ void mma16816(float* c, const uint32_t* a, const uint32_t* b) {
    asm volatile("mma.sync.aligned.m16n8k16.row.col.f32.bf16.bf16.f32 "
                 "{%0,%1,%2,%3}, {%4,%5,%6,%7}, {%8,%9}, {%0,%1,%2,%3};"
                 : "+f"(c[0]), "+f"(c[1]), "+f"(c[2]), "+f"(c[3])
                 : "r"(a[0]), "r"(a[1]), "r"(a[2]), "r"(a[3]), "r"(b[0]), "r"(b[1]));
}
// chunk pairing: c<12 -> (hiA,hiB); 12..23 -> (hiA,loB); 24..35 -> (loA,hiB)
__device__ __forceinline__ int a_chunk(int c) { int ci = c % 12; return (c < 24) ? ci : 12 + ci; }
__device__ __forceinline__ int b_chunk(int c) { int ci = c % 12; return (c >= 12 && c < 24) ? 12 + ci : ci; }
// order-preserving float<->uint key
__device__ __forceinline__ unsigned fkey(float f) {
    unsigned u = __float_as_uint(f);
    return (u & 0x80000000u) ? ~u : (u | 0x80000000u);
}
__device__ __forceinline__ float funkey(unsigned u) {
    return __uint_as_float((u & 0x80000000u) ? (u & 0x7fffffffu) : ~u);
}

union BF8 { __nv_bfloat16 h[8]; uint4 u; };

// ---------------------------------------------------------------------------
// Kernel 0 (fused): blocks [0,CC): normalize proto row, split bf16, write
// g_Bb row [hi|lo]. Blocks [CC,CC+BB): compaction + exact random top-K.
// ---------------------------------------------------------------------------
__global__ void k_prep(const float* __restrict__ p,
                       const int* __restrict__ targets,
                       const float* __restrict__ rsc) {
    int tid = threadIdx.x;
    if (blockIdx.x < CC) {
        int e = blockIdx.x;
        const float4* row = (const float4*)(p + (size_t)e * DD);
        float4 v0 = make_float4(0,0,0,0), v1 = make_float4(0,0,0,0);
        float ss = 0.f;
        if (tid < 96) {
            v0 = row[tid * 2]; v1 = row[tid * 2 + 1];
            ss = v0.x*v0.x + v0.y*v0.y + v0.z*v0.z + v0.w*v0.w
               + v1.x*v1.x + v1.y*v1.y + v1.z*v1.z + v1.w*v1.w;
        }
        for (int o = 16; o > 0; o >>= 1) ss += __shfl_xor_sync(0xffffffffu, ss, o);
        __shared__ float sW[8]; __shared__ float sInv;
        if ((tid & 31) == 0) sW[tid >> 5] = ss;
        __syncthreads();
        if (tid == 0) {
            float t = 0.f;
            for (int w = 0; w < 8; w++) t += sW[w];
            sInv = 1.0f / fmaxf(sqrtf(t), 1e-12f);
        }
        __syncthreads();
        if (tid < 96) {
            float inv = sInv;
            float v[8] = {v0.x*inv, v0.y*inv, v0.z*inv, v0.w*inv,
                          v1.x*inv, v1.y*inv, v1.z*inv, v1.w*inv};
            BF8 hi, lo;
#pragma unroll
            for (int j = 0; j < 8; j++) {
                hi.h[j] = __float2bfloat16(v[j]);
                lo.h[j] = __float2bfloat16(v[j] - __bfloat162float(hi.h[j]));
            }
            unsigned char* dst = g_Bb + (size_t)e * ROWB + tid * 16;
            *(uint4*)(dst)            = hi.u;   // hi segment
            *(uint4*)(dst + DD * 2)   = lo.u;   // lo segment
        }
        return;
    }

    // ---- per-batch compaction + exact random top-KRAND ----
    int b = blockIdx.x - CC;
    __shared__ unsigned int skey[CC];
    __shared__ unsigned char sfl[CC];
    __shared__ int sW[8];
    __shared__ int sOut;

    int lane = tid & 31, wid = tid >> 5;
    int e0 = tid * 4;
    unsigned int key[4]; int posf[4]; int cnt = 0;
#pragma unroll
    for (int j = 0; j < 4; j++) {
        int e = e0 + j;
        int isPos = (targets[b * CC + e] != 0);
        posf[j] = isPos; cnt += isPos;
        unsigned int k = isPos ? 0u : (__float_as_uint(rsc[b * CC + e]) + 1u);
        key[j] = k; skey[e] = k;
    }
    int inc = cnt;
    for (int o = 1; o < 32; o <<= 1) {
        int v = __shfl_up_sync(0xffffffffu, inc, o);
        if (lane >= o) inc += v;
    }
    if (lane == 31) sW[wid] = inc;
    __syncthreads();
    if (tid == 0) {
        int acc = 0;
        for (int w = 0; w < 8; w++) { int v = sW[w]; sW[w] = acc; acc += v; }
        g_posCount[b] = acc;
    }
    __syncthreads();
    int rank = sW[wid] + inc - cnt;
#pragma unroll
    for (int j = 0; j < 4; j++) {
        if (posf[j]) {
            if (rank < SLOTS_PER_B) g_posList[b * SLOTS_PER_B + rank] = e0 + j;
            rank++;
        }
    }
    __syncthreads();

    unsigned lo = 0u, hi = 0xFFFFFFFFu;
    while (hi - lo > 1u) {
        unsigned mid = lo + ((hi - lo) >> 1);
        int c4 = 0;
#pragma unroll
        for (int j = 0; j < 4; j++) c4 += (key[j] >= mid);
        c4 = __reduce_add_sync(0xffffffffu, c4);
        if (lane == 0) sW[wid] = c4;
        __syncthreads();
        int total = sW[0]+sW[1]+sW[2]+sW[3]+sW[4]+sW[5]+sW[6]+sW[7];
        if (total >= KRAND) lo = mid; else hi = mid;
        __syncthreads();
    }
    unsigned V = lo;
    int both4 = 0;
#pragma unroll
    for (int j = 0; j < 4; j++) both4 += (key[j] > V) * 2048 + (key[j] == V);
    both4 = __reduce_add_sync(0xffffffffu, both4);
    if (lane == 0) sW[wid] = both4;
    __syncthreads();
    if (tid == 0) { int t = 0; for (int w = 0; w < 8; w++) t += sW[w]; sOut = t; }
    __syncthreads();
    int n_gt = sOut / 2048;
    int n_eq = sOut % 2048;
    int rrem = KRAND - n_gt;

    if (n_eq == rrem) {
#pragma unroll
        for (int j = 0; j < 4; j++) sfl[e0 + j] = (key[j] >= V) ? 1 : 0;
        __syncthreads();
    } else {
#pragma unroll
        for (int j = 0; j < 4; j++) sfl[e0 + j] = (key[j] > V) ? 1 : 0;
        __syncthreads();
        if (tid == 0) {
            int rem = rrem;
            for (int e = 0; e < CC && rem > 0; e++)
                if (skey[e] == V) { sfl[e] = 1; rem--; }
        }
        __syncthreads();
    }
#pragma unroll
    for (int j = 0; j < 4; j++) g_randFlag[b * CC + e0 + j] = sfl[e0 + j];
}

// ---------------------------------------------------------------------------
// Kernel 1: gather + normalize positive anchor rows, split bf16, write
// g_Ab row [hi|lo].
// ---------------------------------------------------------------------------
__global__ void k_norm_f(const float* __restrict__ f) {
    int i = blockIdx.x;
    int b = i >> 7, r = i & 127;
    int cnt = g_posCount[b]; if (cnt > SLOTS_PER_B) cnt = SLOTS_PER_B;
    if (r >= cnt) return;
    int c = g_posList[i];
    int tid = threadIdx.x;

    const float4* src = (const float4*)(f + (size_t)(b * CC + c) * DD);
    float4 v0 = make_float4(0,0,0,0), v1 = make_float4(0,0,0,0);
    float ss = 0.f;
    if (tid < 96) {
        v0 = src[tid * 2]; v1 = src[tid * 2 + 1];
        ss = v0.x*v0.x + v0.y*v0.y + v0.z*v0.z + v0.w*v0.w
           + v1.x*v1.x + v1.y*v1.y + v1.z*v1.z + v1.w*v1.w;
    }
    for (int o = 16; o > 0; o >>= 1) ss += __shfl_xor_sync(0xffffffffu, ss, o);
    __shared__ float sW[4]; __shared__ float sInv;
    if ((tid & 31) == 0) sW[tid >> 5] = ss;
    __syncthreads();
    if (tid == 0) sInv = 1.0f / fmaxf(sqrtf(sW[0]+sW[1]+sW[2]+sW[3]), 1e-12f);
    __syncthreads();
    if (tid >= 96) return;
    float inv = sInv;
    float v[8] = {v0.x*inv, v0.y*inv, v0.z*inv, v0.w*inv,
                  v1.x*inv, v1.y*inv, v1.z*inv, v1.w*inv};
    BF8 hi, lo;
#pragma unroll
    for (int j = 0; j < 8; j++) {
        hi.h[j] = __float2bfloat16(v[j]);
        lo.h[j] = __float2bfloat16(v[j] - __bfloat162float(hi.h[j]));
    }
    unsigned char* dst = g_Ab + (size_t)i * ROWB + tid * 16;
    *(uint4*)(dst)            = hi.u;   // hi segment
    *(uint4*)(dst + DD * 2)   = lo.u;   // lo segment
}

// ---------------------------------------------------------------------------
// Kernel 2: bf16 tensor-core GEMM via mma.sync m16n8k16, split-K x2.
// Grid (16, 8, 2): CTA = (batch, 128-proto tile, K half). 2 CTAs/SM.
// Chunk pairing tables map virtual chunks -> [hi|lo] row offsets.
// ---------------------------------------------------------------------------
__global__ void __launch_bounds__(256, 2) k_gemm_mma() {
    extern __shared__ __align__(16) unsigned char dynsm[];
    int m = blockIdx.x;
    int cnt = g_posCount[m]; if (cnt <= 0) return;
    if (cnt > SLOTS_PER_B) cnt = SLOTS_PER_B;
    int eBase = blockIdx.y * 128;
    int z = blockIdx.z;
    int cBeg = z * KSPLIT, cEnd = cBeg + KSPLIT;
    float* outS = z ? g_S1 : g_S0;

    int tid = threadIdx.x, lane = tid & 31, wid = tid >> 5;
    int wm = (wid & 1) * 64, wn = (wid >> 1) * 32;

    uint32_t sbase = smem_u32(dynsm);
    const unsigned char* gA = g_Ab + (size_t)m * 128 * ROWB;
    const unsigned char* gB = g_Bb + (size_t)eBase * ROWB;

    float acc[4][4][4];
#pragma unroll
    for (int i = 0; i < 4; i++)
#pragma unroll
        for (int j = 0; j < 4; j++)
#pragma unroll
            for (int q = 0; q < 4; q++) acc[i][j][q] = 0.f;

    auto copy_chunk = [&](int c, int st) {
        uint32_t sA = sbase + st * (2 * TILE_BYTES);
        uint32_t sB = sA + TILE_BYTES;
        int ao = a_chunk(c) * 128, bo = b_chunk(c) * 128;
#pragma unroll
        for (int i = 0; i < 4; i++) {
            int idx = tid + i * 256;
            int row = idx >> 3, seg = idx & 7;
            uint32_t so = (uint32_t)((row << 3) + (seg ^ (row & 7))) * 16;
            size_t rb = (size_t)row * ROWB + seg * 16;
            cp16(sA + so, gA + rb + ao);
            cp16(sB + so, gB + rb + bo);
        }
        asm volatile("cp.async.commit_group;" ::: "memory");
    };

    copy_chunk(cBeg, 0);
    for (int c = cBeg; c < cEnd; c++) {
        int cur = c & 1;
        if (c + 1 < cEnd) copy_chunk(c + 1, cur ^ 1);
        if (c + 1 < cEnd)
            asm volatile("cp.async.wait_group 1;" ::: "memory");
        else
            asm volatile("cp.async.wait_group 0;" ::: "memory");
        __syncthreads();

        uint32_t sA = sbase + cur * (2 * TILE_BYTES);
        uint32_t sB = sA + TILE_BYTES;
#pragma unroll
        for (int ks = 0; ks < 4; ks++) {
            uint32_t a[4][4], b[4][2];
#pragma unroll
            for (int mi = 0; mi < 4; mi++) {
                int row = wm + mi * 16 + (lane & 15);
                int kseg = 2 * ks + (lane >> 4);
                ldsm_x4(a[mi][0], a[mi][1], a[mi][2], a[mi][3],
                        sA + (uint32_t)((row << 3) + (kseg ^ (row & 7))) * 16);
            }
#pragma unroll
            for (int ni = 0; ni < 4; ni++) {
                int rn = wn + ni * 8 + (lane & 7);
                int kseg = 2 * ks + ((lane >> 3) & 1);
                ldsm_x2(b[ni][0], b[ni][1],
                        sB + (uint32_t)((rn << 3) + (kseg ^ (rn & 7))) * 16);
            }
#pragma unroll
            for (int mi = 0; mi < 4; mi++)
#pragma unroll
                for (int ni = 0; ni < 4; ni++)
                    mma16816(acc[mi][ni], a[mi], b[ni]);
        }
        __syncthreads();
    }

    int qr = lane >> 2, qc = (lane & 3) * 2;
#pragma unroll
    for (int mi = 0; mi < 4; mi++) {
#pragma unroll
        for (int ni = 0; ni < 4; ni++) {
            int r0 = wm + mi * 16 + qr;
            int col = eBase + wn + ni * 8 + qc;
            if (r0 < cnt)
                *(float2*)(outS + (size_t)(m * 128 + r0) * CC + col)
                    = make_float2(acc[mi][ni][0], acc[mi][ni][1]);
            if (r0 + 8 < cnt)
                *(float2*)(outS + (size_t)(m * 128 + r0 + 8) * CC + col)
                    = make_float2(acc[mi][ni][2], acc[mi][ni][3]);
        }
    }
}

// ---------------------------------------------------------------------------
// Kernel 3: per positive anchor: top-KHARD exp-sum via 3-pass 256-bin
// histogram descent + random-set exp sum -> loss term. Sums split-K partials.
// ---------------------------------------------------------------------------
__global__ void k_select(const int* __restrict__ targets) {
    int i = blockIdx.x;
    int b = i >> 7, r = i & 127;
    int cnt = g_posCount[b]; if (cnt > SLOTS_PER_B) cnt = SLOTS_PER_B;
    int tid = threadIdx.x;
    if (r >= cnt) { if (tid == 0) g_term[i] = 0.f; return; }
    int c = g_posList[i];

    __shared__ int hist[256];
    __shared__ unsigned sWmax[8];
    __shared__ unsigned sWmin[8];
    __shared__ int sQA[2];
    __shared__ float sWf[8];

    int lane = tid & 31, wid = tid >> 5;

    float4 sa = *((const float4*)(g_S0 + (size_t)i * CC) + tid);
    float4 sb = *((const float4*)(g_S1 + (size_t)i * CC) + tid);
    int4   t4 = *((const int4*)(targets + b * CC) + tid);
    uchar4 r4 = *((const uchar4*)(g_randFlag + b * CC) + tid);
    float s[4] = {sa.x + sb.x, sa.y + sb.y, sa.z + sb.z, sa.w + sb.w};
    int neg[4] = {t4.x == 0, t4.y == 0, t4.z == 0, t4.w == 0};
    int fl[4]  = {r4.x, r4.y, r4.z, r4.w};
    unsigned key[4];
#pragma unroll
    for (int j = 0; j < 4; j++) key[j] = neg[j] ? fkey(s[j]) : 0u;

    unsigned mk = max(max(key[0], key[1]), max(key[2], key[3]));
    unsigned nk0 = neg[0] ? key[0] : 0xffffffffu;
    unsigned nk1 = neg[1] ? key[1] : 0xffffffffu;
    unsigned nk2 = neg[2] ? key[2] : 0xffffffffu;
    unsigned nk3 = neg[3] ? key[3] : 0xffffffffu;
    unsigned nk = min(min(nk0, nk1), min(nk2, nk3));
    mk = __reduce_max_sync(0xffffffffu, mk);
    nk = __reduce_min_sync(0xffffffffu, nk);
    if (lane == 0) { sWmax[wid] = mk; sWmin[wid] = nk; }
    __syncthreads();
    unsigned mAll = sWmax[0], nAll = sWmin[0];
#pragma unroll
    for (int w = 1; w < 8; w++) { mAll = max(mAll, sWmax[w]); nAll = min(nAll, sWmin[w]); }
    float M = funkey(mAll);

    // 3-pass histogram descent: cell [lo, lo+range) always satisfies
    // above = count(key >= lo+range) < KHARD <= above + count(in cell)
    unsigned lo = nAll;
    unsigned range = mAll - nAll + 1u;
    unsigned step = 1u;
    int above = 0;
#pragma unroll
    for (int pass = 0; pass < 3; pass++) {
        step = range / 256u + 1u;
        hist[tid] = 0;
        __syncthreads();
#pragma unroll
        for (int j = 0; j < 4; j++) {
            unsigned d = key[j] - lo;            // wraps huge if key < lo
            if (d < range) atomicAdd(&hist[d / step], 1);
        }
        __syncthreads();
        if (wid == 0) {
            int h[8]; int ssum = 0;
            int base = lane * 8;
#pragma unroll
            for (int q = 0; q < 8; q++) { h[q] = hist[base + q]; ssum += h[q]; }
            int suf = ssum;
            for (int o = 1; o < 32; o <<= 1) {
                int v = __shfl_down_sync(0xffffffffu, suf, o);
                if (lane + o < 32) suf += v;
            }
            int hiAbove = above + suf - ssum;
            if (above + suf >= KHARD && hiAbove < KHARD) {   // exactly one lane
                int acc = hiAbove;
                int q = 7;
                for (; q > 0; q--) {
                    if (acc + h[q] >= KHARD) break;
                    acc += h[q];
                }
                sQA[0] = base + q;
                sQA[1] = acc;
            }
        }
        __syncthreads();
        int Q = sQA[0]; above = sQA[1];
        lo = lo + (unsigned)Q * step;
        range = step;
        __syncthreads();
    }
    unsigned Hi = lo + step;
    int rem = KHARD - above;                     // >= 1 ties in [lo, Hi)

    float es = 0.f;
#pragma unroll
    for (int j = 0; j < 4; j++) {
        float e = __expf((s[j] - M) * TAU_INV);
        if (key[j] >= Hi) es += e;
        if (fl[j])        es += e;
    }
    for (int o = 16; o > 0; o >>= 1) es += __shfl_xor_sync(0xffffffffu, es, o);
    if (lane == 0) sWf[wid] = es;
    __syncthreads();

    if (tid == 0) {
        float su = sWf[0]+sWf[1]+sWf[2]+sWf[3]+sWf[4]+sWf[5]+sWf[6]+sWf[7];
        su += (float)rem * __expf((funkey(lo) - M) * TAU_INV);
        size_t pidx = (size_t)i * CC + c;
        float pos = (g_S0[pidx] + g_S1[pidx]) * TAU_INV;
        float lse = M * TAU_INV + __logf(su);
        float d = lse - pos;
        float term = (d > 0.f) ? d + log1pf(__expf(-d)) : log1pf(__expf(d));
        g_term[i] = term;
    }
}

// ---------------------------------------------------------------------------
// Kernel 4: deterministic final reduction -> scalar loss
// ---------------------------------------------------------------------------
__global__ void k_final(float* __restrict__ out) {
    __shared__ float sbs[BB];
    int wid = threadIdx.x >> 5, lane = threadIdx.x & 31;
    float s = 0.f;
    for (int r = lane; r < SLOTS_PER_B; r += 32) s += g_term[wid * SLOTS_PER_B + r];
    for (int o = 16; o > 0; o >>= 1) s += __shfl_xor_sync(0xffffffffu, s, o);
    if (lane == 0) sbs[wid] = s;
    __syncthreads();
    if (threadIdx.x == 0) {
        float tot = 0.f;
        for (int b = 0; b < BB; b++) {
            int pc = g_posCount[b]; if (pc < 1) pc = 1;
            tot += sbs[b] / (float)pc;
        }
        out[0] = tot / (float)BB;
    }
}

extern "C" void kernel_launch(void* const* d_in, const int* in_sizes, int n_in,
                              void* d_out, int out_size) {
    const float* f       = (const float*)d_in[0];   // (B,C,D)
    const float* p       = (const float*)d_in[1];   // (C,D)
    const int*   targets = (const int*)  d_in[2];   // (B,C)
    const float* rsc     = (const float*)d_in[3];   // (B,C)
    float* out = (float*)d_out;

    cudaFuncSetAttribute(k_gemm_mma, cudaFuncAttributeMaxDynamicSharedMemorySize, DYN_SMEM);

    k_prep<<<CC + BB, 256>>>(p, targets, rsc);
    k_norm_f<<<MAXP, 128>>>(f);
    k_gemm_mma<<<dim3(BB, CC / 128, 2), 256, DYN_SMEM>>>();
    k_select<<<MAXP, 256>>>(targets);
    k_final<<<1, 512>>>(out);
}